// round 9
// baseline (speedup 1.0000x reference)
#include <cuda_runtime.h>
#include <cstdint>

#define LROW 4096
#define THREADS 256
#define VPT (LROW / 4 / THREADS)   // 16B quads per thread = 4
#define FULLW 0xffffffffu
#define MAXROWS 16384

// per-row cutoff scratch (static device global: allocation rules)
__device__ int g_cutoff[MAXROWS];

// ---------------------------------------------------------------------------
// Kernel A: one warp per row. 3-round narrow ballot search for
// len = index of first True (mask is monotone tail padding, len in [1, L]).
// Writes cutoff[row] = min(ceil(float(len)*0.7f), L-1).
// Reads ~34 sectors per row (~1.1 KB) instead of the 16 KB row.
// ---------------------------------------------------------------------------
__global__ void __launch_bounds__(THREADS)
probe_kernel(const int* __restrict__ mask, int nrows) {
    const int lane = threadIdx.x & 31;
    const int row = blockIdx.x * (THREADS / 32) + (threadIdx.x >> 5);
    if (row >= nrows) return;
    const int* m = mask + (size_t)row * LROW;

    // round 1: stride-128 probes; lane 0 -> m[0] = 0 always (len >= 1)
    const unsigned b1 = __ballot_sync(FULLW, m[128 * lane] != 0);
    const int base = b1 ? 128 * (__ffs(b1) - 2) : (LROW - 128); // len in (base, base+128]

    // round 2: stride-4 probes base+4 .. base+128 (clamped)
    int p2 = base + 4 * (lane + 1);
    if (p2 > LROW - 1) p2 = LROW - 1;
    const unsigned b2 = __ballot_sync(FULLW, m[p2] != 0);

    int len;
    if (b2 == 0) {
        len = LROW;                                   // all-False row
    } else {
        const int base2 = base + 4 * (__ffs(b2) - 1); // len in (base2, base2+4]
        int p3 = base2 + lane;
        if (p3 > LROW - 1) p3 = LROW - 1;
        const bool hit3 = (lane >= 1 && lane < 4) && (m[p3] != 0);
        const unsigned b3 = __ballot_sync(FULLW, hit3);
        len = b3 ? (base2 + __ffs(b3) - 1) : (base2 + 4);
    }

    if (lane == 0) {
        int c = (int)ceilf((float)len * 0.7f);        // f32 math like reference
        if (c > LROW - 1) c = LROW - 1;
        g_cutoff[row] = c;
    }
}

// ---------------------------------------------------------------------------
// Kernel B: dependency-free streaming. Copies x and writes
// new_mask[j] = (j >= cutoff) as 0.0/1.0 floats. No mask reads at all.
// ---------------------------------------------------------------------------
__global__ void __launch_bounds__(THREADS)
stream_kernel(const float4* __restrict__ x,
              float4* __restrict__ out_x,
              float4* __restrict__ out_m) {
    const int row = blockIdx.x;
    const int tid = threadIdx.x;
    const size_t rbase = (size_t)row * (LROW / 4);   // in 16B quads

    const int cutoff = g_cutoff[row];                // uniform broadcast load

    // x row loads (independent; fill the pipe under the cutoff load)
    float4 xv[VPT];
#pragma unroll
    for (int i = 0; i < VPT; i++)
        xv[i] = x[rbase + tid + i * THREADS];

#pragma unroll
    for (int i = 0; i < VPT; i++) {
        const int idx = tid + i * THREADS;
        out_x[rbase + idx] = xv[i];

        const int j = idx * 4;
        float4 o;
        o.x = (j + 0 >= cutoff) ? 1.0f : 0.0f;
        o.y = (j + 1 >= cutoff) ? 1.0f : 0.0f;
        o.z = (j + 2 >= cutoff) ? 1.0f : 0.0f;
        o.w = (j + 3 >= cutoff) ? 1.0f : 0.0f;
        out_m[rbase + idx] = o;
    }
}

extern "C" void kernel_launch(void* const* d_in, const int* in_sizes, int n_in,
                              void* d_out, int out_size) {
    const float* x    = (const float*)d_in[0];
    const int*   mask = (const int*)d_in[1];        // bool transported as int32
    const long long n = (long long)in_sizes[0];     // B*L elements of x
    const int B = (int)(n / LROW);

    float* out_x = (float*)d_out;
    float* out_m = out_x + n;                        // [x | new_mask]

    probe_kernel<<<(B + (THREADS / 32) - 1) / (THREADS / 32), THREADS>>>(mask, B);
    stream_kernel<<<B, THREADS>>>((const float4*)x,
                                  (float4*)out_x, (float4*)out_m);
}